// round 10
// baseline (speedup 1.0000x reference)
#include <cuda_runtime.h>

// SpMM: y = x @ W^T, W in CSR with uniform 128 nnz/row, indices SORTED per row.
//   x:       [512, 2048] f32
//   data:    [262144]    f32
//   indices: [262144]    i32
//   indptr:  [2049]      i32
//   y (out): [512, 2048] f32
//
// R8 design:
//   CH=32 tokens per block -> a column's token slice is 128B = all 32 smem
//   banks. Warp = 4 rows x 8 token-octets; each LDS.128 phase = 8 lanes of
//   ONE row reading the 8 swizzled 16B slots of one column => conflict-free
//   gathers, data-independent (R6 paid ~1.5x here).
//   x staged in column-HALVES (1024 cols x 32 tok = 128KB) over two passes;
//   sorted indices make each half a contiguous k-segment found by one binary
//   search per row. 1024-thread blocks (128 rows) keep total staging at 64MB
//   and raise occupancy to 32 warps/SM.

#define NTOK    512
#define NIN     2048
#define NOUT    2048
#define CH      32                    // tokens per block
#define HALF    1024                  // cols staged per pass
#define RPB     128                   // rows per block
#define THREADS 1024
#define SMEM_WORDS (HALF * CH)        // 32768 floats = 128 KB

// Column c (local to the staged half) owns words [c*32, c*32+32) = banks
// 0..31. Token-octet q lives at slot (q ^ c) & 7 (4 words each): staging
// stores by 8 consecutive threads (consecutive c, same q) hit all 8 slots ->
// conflict-free; gather phase (one c, tg=0..7) hits all 8 slots -> conflict-free.
__device__ __forceinline__ int sx_word(int c, int q) {
    return (c << 5) + (((q ^ c) & 7) << 2);
}

__global__ void __launch_bounds__(THREADS, 1)
spmm_csr_kernel(const float* __restrict__ x,
                const float* __restrict__ data,
                const int*   __restrict__ indices,
                const int*   __restrict__ indptr,
                float*       __restrict__ y)
{
    extern __shared__ float s_x[];

    const int tid     = threadIdx.x;
    const int lane    = tid & 31;
    const int tg      = tid & 7;      // token-octet (4 tokens each)
    const int row_sub = tid >> 3;     // 0..127
    const int row     = blockIdx.x * RPB + row_sub;
    const int tok0    = blockIdx.y * CH;

    const int base = __ldg(&indptr[row]);
    const int kend = __ldg(&indptr[row + 1]);

    // indices sorted per row: find first k with col >= HALF (half boundary).
    int lo = base, hi = kend;
    while (lo < hi) {
        const int mid = (lo + hi) >> 1;
        if (__ldg(&indices[mid]) < HALF) lo = mid + 1; else hi = mid;
    }
    const int split = lo;

    float4 acc = make_float4(0.f, 0.f, 0.f, 0.f);

    #pragma unroll
    for (int h = 0; h < 2; ++h) {
        // ---------- stage half h of x for this token chunk ----------
        __syncthreads();              // previous pass's readers done
        {
            const int gc0 = h * HALF;
            #pragma unroll
            for (int it = 0; it < (HALF * 8) / THREADS; ++it) {   // 8 iters
                const int i = tid + it * THREADS;
                const int q = i >> 10;            // 0..7
                const int c = i & (HALF - 1);
                const float* xp = x + (size_t)(tok0 + (q << 2)) * NIN + gc0 + c;
                float4 v;
                v.x = __ldg(xp);
                v.y = __ldg(xp + NIN);
                v.z = __ldg(xp + 2 * NIN);
                v.w = __ldg(xp + 3 * NIN);
                *reinterpret_cast<float4*>(&s_x[sx_word(c, q)]) = v;
            }
        }
        __syncthreads();

        // ---------- gather + accumulate over this row's segment ----------
        const int s   = h ? split : base;
        const int e   = h ? kend  : split;
        const int len = e - s;

        // warp-uniform trip count: max segment length over the 4 rows
        int ml = len;
        ml = max(ml, __shfl_xor_sync(0xffffffffu, ml, 8));
        ml = max(ml, __shfl_xor_sync(0xffffffffu, ml, 16));

        for (int c0 = 0; c0 < ml; c0 += 8) {
            // lane tg prefetches the (c0+tg)-th nnz of its row: per warp-instr
            // 4 rows x 32B consecutive -> 4 sectors.
            const int  kk = s + c0 + tg;
            const bool ok = (c0 + tg) < len;
            float w8 = 0.f;
            int   c8 = 0;
            if (ok) {
                w8 = __ldg(&data[kk]);
                c8 = __ldg(&indices[kk]);
            }
            #pragma unroll
            for (int j = 0; j < 8; ++j) {
                const int   src = (lane & ~7) | j;        // same row, holder j
                const float w   = __shfl_sync(0xffffffffu, w8, src);
                const int   cc  = __shfl_sync(0xffffffffu, c8, src);
                if ((c0 + j) < len) {
                    const int cl = cc & (HALF - 1);
                    const float4 v =
                        *reinterpret_cast<const float4*>(&s_x[sx_word(cl, tg)]);
                    acc.x = fmaf(w, v.x, acc.x);
                    acc.y = fmaf(w, v.y, acc.y);
                    acc.z = fmaf(w, v.z, acc.z);
                    acc.w = fmaf(w, v.w, acc.w);
                }
            }
        }
    }

    // ---------- writeback: y[tok][row], tokens tok0 + 4*tg + {0..3} ----------
    // Lanes {tg, tg+8, tg+16, tg+24} write 4 consecutive rows of one token.
    float* yp = y + (size_t)(tok0 + (tg << 2)) * NOUT + row;
    yp[0]                = acc.x;
    yp[NOUT]             = acc.y;
    yp[2 * (size_t)NOUT] = acc.z;
    yp[3 * (size_t)NOUT] = acc.w;
}

extern "C" void kernel_launch(void* const* d_in, const int* in_sizes, int n_in,
                              void* d_out, int out_size)
{
    const float* x       = (const float*)d_in[0];
    const float* data    = (const float*)d_in[1];
    const int*   indices = (const int*)d_in[2];
    const int*   indptr  = (const int*)d_in[3];
    float*       y       = (float*)d_out;

    cudaFuncSetAttribute(spmm_csr_kernel,
                         cudaFuncAttributeMaxDynamicSharedMemorySize,
                         SMEM_WORDS * (int)sizeof(float));

    dim3 grid(NOUT / RPB, NTOK / CH);   // (16, 16) = 256 blocks
    spmm_csr_kernel<<<grid, THREADS, SMEM_WORDS * sizeof(float)>>>(
        x, data, indices, indptr, y);
}

// round 12
// speedup vs baseline: 1.0900x; 1.0900x over previous
#include <cuda_runtime.h>

// SpMM: y = x @ W^T, W CSR, uniform 128 nnz/row, indices SORTED per row.
//   x [512,2048] f32, data [262144] f32, indices [262144] i32,
//   indptr [2049] i32, y [512,2048] f32.
//
// R10: CH=64 tokens/block, x staged in four 512-col quarters (128KB each).
// Lane = (row, octet o): accumulates 8 tokens via 2x LDS.128 per nnz.
// No shuffles: all 8 lanes of a row issue the same vector LDG for the
// (w,col) chunk (warp-level broadcast). Out-of-segment nnz killed by a
// per-lane predicate that also gates the LDS (no wasted smem bytes).

#define NTOK    512
#define NIN     2048
#define NOUT    2048
#define CH      64                    // tokens per block
#define CQ      512                   // cols per staged quarter
#define NQ      4
#define RPB     128                   // rows per block
#define THREADS 1024
#define SMEM_WORDS (CQ * CH)          // 32768 floats = 128 KB

// Storage position of (local col c, token-slot s), s in [0,16):
//   word = c*64 + perm*4,  perm = ((s&7)^(c&7)) | (s&8)
// Staging (consecutive c, fixed s): perm low bits are a bijection of c&7 ->
// 8 float4 stores tile all 32 banks. Gather (fixed c, lane o reads s=o and
// s=o+8): 8 lanes hit 8 distinct perms -> conflict-free; second read is
// first address + 128B (LDS immediate offset).
__device__ __forceinline__ float f4c(const float4& v, int c) {
    return c == 0 ? v.x : c == 1 ? v.y : c == 2 ? v.z : v.w;
}
__device__ __forceinline__ int i4c(const int4& v, int c) {
    return c == 0 ? v.x : c == 1 ? v.y : c == 2 ? v.z : v.w;
}

__global__ void __launch_bounds__(THREADS, 1)
spmm_csr_kernel(const float* __restrict__ x,
                const float* __restrict__ data,
                const int*   __restrict__ indices,
                const int*   __restrict__ indptr,
                float*       __restrict__ y)
{
    extern __shared__ float s_x[];

    const int tid  = threadIdx.x;
    const int lane = tid & 31;
    const int o    = lane & 7;        // token-octet within row
    const int row  = blockIdx.x * RPB + (tid >> 3);
    const int tok0 = blockIdx.y * CH;

    const int base = __ldg(&indptr[row]);
    const int kend = __ldg(&indptr[row + 1]);

    // Quarter split points: first k with indices[k] >= q*512.
    int sp[NQ + 1];
    sp[0] = base; sp[NQ] = kend;
    #pragma unroll
    for (int q = 1; q < NQ; ++q) {
        int lo = base, hi = kend;
        const int bound = q * CQ;
        while (lo < hi) {
            const int mid = (lo + hi) >> 1;
            if (__ldg(&indices[mid]) < bound) lo = mid + 1; else hi = mid;
        }
        sp[q] = lo;
    }

    float4 accA = make_float4(0.f, 0.f, 0.f, 0.f);   // tokens tok0+4o..+3
    float4 accB = make_float4(0.f, 0.f, 0.f, 0.f);   // tokens tok0+4(o+8)..+3

    #pragma unroll
    for (int q = 0; q < NQ; ++q) {
        __syncthreads();              // previous quarter's readers done
        // ---------------- stage quarter q: x[tok0..tok0+63][q*512..+512) ----
        {
            const int gc0 = q * CQ;
            #pragma unroll
            for (int it = 0; it < (CQ * 16) / THREADS; ++it) {   // 8 iters
                const int i = tid + it * THREADS;
                const int c = i & (CQ - 1);
                const int s = i >> 9;                 // 0..15
                const float* xp = x + (size_t)(tok0 + (s << 2)) * NIN + gc0 + c;
                float4 v;
                v.x = __ldg(xp);
                v.y = __ldg(xp + NIN);
                v.z = __ldg(xp + 2 * NIN);
                v.w = __ldg(xp + 3 * NIN);
                const int wrd = (c << 6) + (((((s & 7) ^ (c & 7))) | (s & 8)) << 2);
                *reinterpret_cast<float4*>(&s_x[wrd]) = v;
            }
        }
        __syncthreads();

        // ---------------- gather this row's segment for quarter q ----------
        const int seg = sp[q];
        const int end = sp[q + 1];
        const int len = end - seg;
        const int kA0 = seg & ~7;                     // 32B-aligned chunk grid
        int trips = (end - kA0 + 7) >> 3;
        if (len == 0) trips = 0;

        int mt = trips;                               // warp-uniform trip count
        mt = max(mt, __shfl_xor_sync(0xffffffffu, mt, 8));
        mt = max(mt, __shfl_xor_sync(0xffffffffu, mt, 16));

        const float4* dp = reinterpret_cast<const float4*>(data + kA0);
        const int4*   ip = reinterpret_cast<const int4*>(indices + kA0);

        for (int t = 0; t < mt; ++t) {
            float4 wa, wb; int4 ca, cb;
            if (t < trips) {
                wa = __ldg(dp + 2 * t); wb = __ldg(dp + 2 * t + 1);
                ca = __ldg(ip + 2 * t); cb = __ldg(ip + 2 * t + 1);
            } else {
                wa = wb = make_float4(0.f, 0.f, 0.f, 0.f);
                ca = cb = make_int4(0, 0, 0, 0);
            }
            const int off0 = kA0 + 8 * t - seg;       // may be negative (front pad)
            #pragma unroll
            for (int j = 0; j < 8; ++j) {
                const bool ok = (unsigned)(off0 + j) < (unsigned)len;
                if (ok) {
                    const int   cc = (j < 4) ? i4c(ca, j) : i4c(cb, j - 4);
                    const float w  = (j < 4) ? f4c(wa, j) : f4c(wb, j - 4);
                    const int   cl = cc & (CQ - 1);
                    const int wrd  = (cl << 6) + ((o ^ (cl & 7)) << 2);
                    const float4 vA = *reinterpret_cast<const float4*>(&s_x[wrd]);
                    const float4 vB = *reinterpret_cast<const float4*>(&s_x[wrd + 32]);
                    accA.x = fmaf(w, vA.x, accA.x);
                    accA.y = fmaf(w, vA.y, accA.y);
                    accA.z = fmaf(w, vA.z, accA.z);
                    accA.w = fmaf(w, vA.w, accA.w);
                    accB.x = fmaf(w, vB.x, accB.x);
                    accB.y = fmaf(w, vB.y, accB.y);
                    accB.z = fmaf(w, vB.z, accB.z);
                    accB.w = fmaf(w, vB.w, accB.w);
                }
            }
        }
    }

    // ---------------- writeback: y[tok][row] ----------------
    float* yp = y + (size_t)(tok0 + (o << 2)) * NOUT + row;
    yp[0]                = accA.x;
    yp[NOUT]             = accA.y;
    yp[2 * (size_t)NOUT] = accA.z;
    yp[3 * (size_t)NOUT] = accA.w;
    float* yp2 = yp + (size_t)32 * NOUT;              // tokens +32
    yp2[0]                = accB.x;
    yp2[NOUT]             = accB.y;
    yp2[2 * (size_t)NOUT] = accB.z;
    yp2[3 * (size_t)NOUT] = accB.w;
}

extern "C" void kernel_launch(void* const* d_in, const int* in_sizes, int n_in,
                              void* d_out, int out_size)
{
    const float* x       = (const float*)d_in[0];
    const float* data    = (const float*)d_in[1];
    const int*   indices = (const int*)d_in[2];
    const int*   indptr  = (const int*)d_in[3];
    float*       y       = (float*)d_out;

    cudaFuncSetAttribute(spmm_csr_kernel,
                         cudaFuncAttributeMaxDynamicSharedMemorySize,
                         SMEM_WORDS * (int)sizeof(float));

    dim3 grid(NOUT / RPB, NTOK / CH);   // (16, 8) = 128 blocks = 1 wave
    spmm_csr_kernel<<<grid, THREADS, SMEM_WORDS * sizeof(float)>>>(
        x, data, indices, indptr, y);
}

// round 13
// speedup vs baseline: 1.1404x; 1.0463x over previous
#include <cuda_runtime.h>

// SpMM: y = x @ W^T, W CSR, uniform 128 nnz/row, indices SORTED per row.
//   x [512,2048] f32, data [262144] f32, indices [262144] i32,
//   indptr [2049] i32, y [512,2048] f32.
//
// R12: CH=32 tokens/block, x staged in two 1024-col halves (128KB each),
// conflict-free swizzle (warp = 4 rows x 8 octets; each LDS.128 phase = 8
// lanes of one row tiling all 32 banks). Broadcast vector LDG for (w,col)
// chunks (no shuffles). Inner loop is BRANCH-FREE: every j executes; out-of-
// segment j's are neutralized by zeroing w with one FSEL (smem read is
// garbage-but-in-bounds, x0 contributes nothing). Per-row exact trip counts;
// all chunk loads stay inside the row's own [base,kend) since base is
// 128-aligned and kend 8-aligned.

#define NTOK    512
#define NIN     2048
#define NOUT    2048
#define CH      32                    // tokens per block
#define HALF    1024                  // cols staged per pass
#define RPB     128                   // rows per block
#define THREADS 1024
#define SMEM_WORDS (HALF * CH)        // 32768 floats = 128 KB

// Column c (local) owns words [c*32, c*32+32) = all 32 banks. Token-octet q
// (4 tokens) lives at slot (q^c)&7. Staging: 8 consecutive threads (consec c,
// fixed q) hit 8 distinct slots -> conflict-free STS.128. Gather: lanes
// o=0..7 of one row read slots (o^c)&7 -> conflict-free LDS.128.
__device__ __forceinline__ float f4c(const float4& v, int c) {
    return c == 0 ? v.x : c == 1 ? v.y : c == 2 ? v.z : v.w;
}
__device__ __forceinline__ int i4c(const int4& v, int c) {
    return c == 0 ? v.x : c == 1 ? v.y : c == 2 ? v.z : v.w;
}

__global__ void __launch_bounds__(THREADS, 1)
spmm_csr_kernel(const float* __restrict__ x,
                const float* __restrict__ data,
                const int*   __restrict__ indices,
                const int*   __restrict__ indptr,
                float*       __restrict__ y)
{
    extern __shared__ float s_x[];

    const int tid  = threadIdx.x;
    const int lane = tid & 31;
    const int o    = lane & 7;        // token-octet within row
    const int row  = blockIdx.x * RPB + (tid >> 3);
    const int tok0 = blockIdx.y * CH;

    const int base = __ldg(&indptr[row]);      // 128-aligned (row*128)
    const int kend = __ldg(&indptr[row + 1]);  // 8-aligned

    // Sorted indices: first k with col >= HALF.
    int lo = base, hi = kend;
    while (lo < hi) {
        const int mid = (lo + hi) >> 1;
        if (__ldg(&indices[mid]) < HALF) lo = mid + 1; else hi = mid;
    }
    const int split = lo;

    float4 acc = make_float4(0.f, 0.f, 0.f, 0.f);  // tokens tok0+4o..+3

    #pragma unroll
    for (int h = 0; h < 2; ++h) {
        __syncthreads();              // previous half's readers done
        // ---------------- stage half h ----------------
        {
            const int gc0 = h * HALF;
            #pragma unroll
            for (int it = 0; it < (HALF * 8) / THREADS; ++it) {   // 8 iters
                const int i = tid + it * THREADS;
                const int c = i & (HALF - 1);
                const int q = i >> 10;            // 0..7
                const float* xp = x + (size_t)(tok0 + (q << 2)) * NIN + gc0 + c;
                float4 v;
                v.x = __ldg(xp);
                v.y = __ldg(xp + NIN);
                v.z = __ldg(xp + 2 * NIN);
                v.w = __ldg(xp + 3 * NIN);
                *reinterpret_cast<float4*>(&s_x[(c << 5) + (((q ^ c) & 7) << 2)]) = v;
            }
        }
        __syncthreads();

        // ---------------- gather this row's segment ----------------
        const int seg = h ? split : base;
        const int end = h ? kend  : split;
        const int len = end - seg;
        const int kA0 = seg & ~7;     // >= base (base 128-aligned)
        // last chunk end = ((end-1)&~7)+8 <= kend (kend 8-aligned): in-bounds.
        const int trips = (len > 0) ? ((end - kA0 + 7) >> 3) : 0;

        const float4* dp = reinterpret_cast<const float4*>(data + kA0);
        const int4*   ip = reinterpret_cast<const int4*>(indices + kA0);

        int d0 = kA0 - seg;           // offset of chunk start vs segment start
        for (int t = 0; t < trips; ++t, d0 += 8) {
            const float4 wa = __ldg(dp + 2 * t);
            const float4 wb = __ldg(dp + 2 * t + 1);
            const int4   ca = __ldg(ip + 2 * t);
            const int4   cb = __ldg(ip + 2 * t + 1);
            #pragma unroll
            for (int j = 0; j < 8; ++j) {
                float w = (j < 4) ? f4c(wa, j) : f4c(wb, j - 4);
                const int cc = (j < 4) ? i4c(ca, j) : i4c(cb, j - 4);
                // branch-free kill of out-of-segment j's
                w = ((unsigned)(d0 + j) < (unsigned)len) ? w : 0.f;
                const int cl  = cc & (HALF - 1);          // in-bounds always
                const int wrd = (cl << 5) + (((o ^ cl) & 7) << 2);
                const float4 v = *reinterpret_cast<const float4*>(&s_x[wrd]);
                acc.x = fmaf(w, v.x, acc.x);
                acc.y = fmaf(w, v.y, acc.y);
                acc.z = fmaf(w, v.z, acc.z);
                acc.w = fmaf(w, v.w, acc.w);
            }
        }
    }

    // ---------------- writeback: y[tok][row], tokens tok0+4o+{0..3} --------
    float* yp = y + (size_t)(tok0 + (o << 2)) * NOUT + row;
    yp[0]                = acc.x;
    yp[NOUT]             = acc.y;
    yp[2 * (size_t)NOUT] = acc.z;
    yp[3 * (size_t)NOUT] = acc.w;
}

extern "C" void kernel_launch(void* const* d_in, const int* in_sizes, int n_in,
                              void* d_out, int out_size)
{
    const float* x       = (const float*)d_in[0];
    const float* data    = (const float*)d_in[1];
    const int*   indices = (const int*)d_in[2];
    const int*   indptr  = (const int*)d_in[3];
    float*       y       = (float*)d_out;

    cudaFuncSetAttribute(spmm_csr_kernel,
                         cudaFuncAttributeMaxDynamicSharedMemorySize,
                         SMEM_WORDS * (int)sizeof(float));

    dim3 grid(NOUT / RPB, NTOK / CH);   // (16, 16) = 256 blocks
    spmm_csr_kernel<<<grid, THREADS, SMEM_WORDS * sizeof(float)>>>(
        x, data, indices, indptr, y);
}